// round 2
// baseline (speedup 1.0000x reference)
#include <cuda_runtime.h>

// Reference collapses analytically:
//   q = x @ Wq^T + bq                      (8x8 GEMV per row)
//   c_w = cos(q_w + phi_w)
//   o[0]   = c1*c2*...*c7
//   o[w]   = c0*...*cw          (w = 1..7)   [Z expectations after CNOT ring]
//   y = o @ Wc^T + bc                      (8x8 GEMV per row)
// k/v branches are dead code in the reference.

#define E 8

__global__ __launch_bounds__(128)
void mhaq_kernel(const float* __restrict__ x,
                 const float* __restrict__ Wq,
                 const float* __restrict__ bq,
                 const float* __restrict__ Wc,
                 const float* __restrict__ bc,
                 const float* __restrict__ phi,
                 float* __restrict__ out,
                 int n_rows)
{
    __shared__ float sWq[64];
    __shared__ float sWc[64];
    __shared__ float sbq[8], sbc[8], sphi[8];

    int t = threadIdx.x;
    if (t < 64) { sWq[t] = Wq[t]; sWc[t] = Wc[t]; }
    if (t < 8)  { sbq[t] = bq[t]; sbc[t] = bc[t]; sphi[t] = phi[t]; }
    __syncthreads();

    int row = blockIdx.x * blockDim.x + t;
    if (row >= n_rows) return;

    // Load one row of x (8 contiguous floats) as 2x float4
    const float4* xp = reinterpret_cast<const float4*>(x) + (size_t)row * 2;
    float4 a = xp[0];
    float4 b = xp[1];
    float xr[E] = {a.x, a.y, a.z, a.w, b.x, b.y, b.z, b.w};

    // q_j = bq_j + sum_k x_k * Wq[j,k];  c_j = cos(q_j + phi_j)
    float c[E];
#pragma unroll
    for (int j = 0; j < E; j++) {
        float q = sbq[j];
#pragma unroll
        for (int k = 0; k < E; k++)
            q = fmaf(xr[k], sWq[j * E + k], q);
        c[j] = cosf(q + sphi[j]);
    }

    // Prefix products: o[w] = c0*...*cw (w>=1), o[0] = c1*...*c7
    float o[E];
    float pre = c[0];
#pragma unroll
    for (int w = 1; w < E; w++) { pre *= c[w]; o[w] = pre; }
    float suf = c[1];
#pragma unroll
    for (int w = 2; w < E; w++) suf *= c[w];
    o[0] = suf;

    // y_j = bc_j + sum_k o_k * Wc[j,k]
    float y[E];
#pragma unroll
    for (int j = 0; j < E; j++) {
        float v = sbc[j];
#pragma unroll
        for (int k = 0; k < E; k++)
            v = fmaf(o[k], sWc[j * E + k], v);
        y[j] = v;
    }

    float4* op = reinterpret_cast<float4*>(out) + (size_t)row * 2;
    op[0] = make_float4(y[0], y[1], y[2], y[3]);
    op[1] = make_float4(y[4], y[5], y[6], y[7]);
}

extern "C" void kernel_launch(void* const* d_in, const int* in_sizes, int n_in,
                              void* d_out, int out_size)
{
    // metadata order: x, Wq, bq, Wk, bk, Wv, bv, Wc, bc, phi
    const float* x   = (const float*)d_in[0];
    const float* Wq  = (const float*)d_in[1];
    const float* bq  = (const float*)d_in[2];
    const float* Wc  = (const float*)d_in[7];
    const float* bc  = (const float*)d_in[8];
    const float* phi = (const float*)d_in[9];
    float* out = (float*)d_out;

    int n_rows = in_sizes[0] / E;   // 32768
    int threads = 128;
    int blocks = (n_rows + threads - 1) / threads;
    mhaq_kernel<<<blocks, threads>>>(x, Wq, bq, Wc, bc, phi, out, n_rows);
}

// round 3
// speedup vs baseline: 1.1077x; 1.1077x over previous
#include <cuda_runtime.h>

// Analytical collapse of the reference:
//   q = x @ Wq^T + bq ;  c_w = cos(q_w + phi_w)
//   o[0] = c1*...*c7 ;  o[w] = c0*...*cw  (w=1..7)   [CNOT-ring Z expectations]
//   y = o @ Wc^T + bc
// k/v are dead code.

#define E 8

__global__ __launch_bounds__(256)
void mhaq_kernel(const float* __restrict__ x,
                 const float* __restrict__ Wq,
                 const float* __restrict__ bq,
                 const float* __restrict__ Wc,
                 const float* __restrict__ bc,
                 const float* __restrict__ phi,
                 float* __restrict__ out,
                 int n_rows)
{
    __shared__ float sWq[64];
    __shared__ float sWc[64];
    __shared__ float sbqp[8];   // bq + phi folded
    __shared__ float sbc[8];

    int t = threadIdx.x;
    if (t < 64) { sWq[t] = Wq[t]; sWc[t] = Wc[t]; }
    if (t < 8)  { sbqp[t] = bq[t] + phi[t]; sbc[t] = bc[t]; }

    int row = blockIdx.x * blockDim.x + t;

    // Issue the global load before the barrier to overlap DRAM latency
    float4 a, b;
    if (row < n_rows) {
        const float4* xp = reinterpret_cast<const float4*>(x) + (size_t)row * 2;
        a = xp[0];
        b = xp[1];
    }
    __syncthreads();
    if (row >= n_rows) return;

    float xr[E] = {a.x, a.y, a.z, a.w, b.x, b.y, b.z, b.w};

    // c_j = __cosf( (x @ Wq^T)_j + bq_j + phi_j )
    float c[E];
#pragma unroll
    for (int j = 0; j < E; j++) {
        float q = sbqp[j];
#pragma unroll
        for (int k = 0; k < E; k++)
            q = fmaf(xr[k], sWq[j * E + k], q);
        c[j] = __cosf(q);
    }

    // Prefix products
    float o[E];
    float pre = c[0];
#pragma unroll
    for (int w = 1; w < E; w++) { pre *= c[w]; o[w] = pre; }
    float suf = c[1];
#pragma unroll
    for (int w = 2; w < E; w++) suf *= c[w];
    o[0] = suf;

    // y = o @ Wc^T + bc
    float y[E];
#pragma unroll
    for (int j = 0; j < E; j++) {
        float v = sbc[j];
#pragma unroll
        for (int k = 0; k < E; k++)
            v = fmaf(o[k], sWc[j * E + k], v);
        y[j] = v;
    }

    float4* op = reinterpret_cast<float4*>(out) + (size_t)row * 2;
    op[0] = make_float4(y[0], y[1], y[2], y[3]);
    op[1] = make_float4(y[4], y[5], y[6], y[7]);
}

extern "C" void kernel_launch(void* const* d_in, const int* in_sizes, int n_in,
                              void* d_out, int out_size)
{
    // metadata order: x, Wq, bq, Wk, bk, Wv, bv, Wc, bc, phi
    const float* x   = (const float*)d_in[0];
    const float* Wq  = (const float*)d_in[1];
    const float* bq  = (const float*)d_in[2];
    const float* Wc  = (const float*)d_in[7];
    const float* bc  = (const float*)d_in[8];
    const float* phi = (const float*)d_in[9];
    float* out = (float*)d_out;

    int n_rows = in_sizes[0] / E;           // 32768
    int threads = 256;
    int blocks = (n_rows + threads - 1) / threads;  // 128 -> one balanced wave on 148 SMs
    mhaq_kernel<<<blocks, threads>>>(x, Wq, bq, Wc, bc, phi, out, n_rows);
}